// round 3
// baseline (speedup 1.0000x reference)
#include <cuda_runtime.h>
#include <math.h>
#include <math_constants.h>

#define SS 2048
#define BB 64
#define HH 1024
#define CH 128
#define CHUNKS (SS/CH)          // 16
#define NBLK1 (BB*CHUNKS)       // 1024
#define REC 1040                // 1024 acc + m + z (padded)

// ---------------- scratch (no allocations allowed) ----------------
__device__ float g_part[NBLK1 * REC];      // ~4.3 MB partial softmax records
__device__ float g_attn[BB * HH];          // attention-pooled context
__device__ float g_mz[BB * 2];             // per-b (max, Z)
__device__ float g_x1[BB * HH];            // fc1 output
__device__ float g_x1p[8 * BB * HH];       // gemm1 k-split partials
__device__ float g_x2[BB * HH];            // bn+tanh output
__device__ float g_x3p[4 * BB * HH];       // gemm2 k-split partials

// ---------------- K1: fused scores + online-softmax weighted sum ----------------
// grid = 1024 (b * 16 chunks), block = 256 (8 warps). Each warp processes 16 rows,
// keeps key and a full-H accumulator in registers (h = j*128 + lane*4 + c).
__global__ __launch_bounds__(256, 2) void k_attn_partial(
    const float* __restrict__ ctx, const float* __restrict__ key,
    const float* __restrict__ mask, float* __restrict__ scores_raw)
{
    int blk = blockIdx.x;
    int b = blk / CHUNKS;
    int chunk = blk % CHUNKS;
    int s0 = chunk * CH;
    int tid = threadIdx.x;
    int w = tid >> 5;
    int lane = tid & 31;

    const float4* keyv = (const float4*)(key + (size_t)b * HH);
    float4 k4[8];
#pragma unroll
    for (int j = 0; j < 8; j++) k4[j] = keyv[j * 32 + lane];

    float4 a4[8];
#pragma unroll
    for (int j = 0; j < 8; j++) a4[j] = make_float4(0.f, 0.f, 0.f, 0.f);
    float m = -3.0e38f, z = 0.f;

    for (int t = 0; t < CH / 8; t++) {
        int s = s0 + w + t * 8;
        const float4* row = (const float4*)(ctx + ((size_t)s * BB + b) * HH);
        float4 r4[8];
#pragma unroll
        for (int j = 0; j < 8; j++) r4[j] = row[j * 32 + lane];

        float p = 0.f;
#pragma unroll
        for (int j = 0; j < 8; j++)
            p += r4[j].x * k4[j].x + r4[j].y * k4[j].y + r4[j].z * k4[j].z + r4[j].w * k4[j].w;
#pragma unroll
        for (int off = 16; off > 0; off >>= 1)
            p += __shfl_xor_sync(0xffffffffu, p, off);

        float score = p + mask[(size_t)b * SS + s];
        if (lane == 0) scores_raw[(size_t)b * SS + s] = score;

        float mn = fmaxf(m, score);
        float alpha = __expf(m - mn);
        float pe = __expf(score - mn);
        z = z * alpha + pe;
#pragma unroll
        for (int j = 0; j < 8; j++) {
            a4[j].x = a4[j].x * alpha + pe * r4[j].x;
            a4[j].y = a4[j].y * alpha + pe * r4[j].y;
            a4[j].z = a4[j].z * alpha + pe * r4[j].z;
            a4[j].w = a4[j].w * alpha + pe * r4[j].w;
        }
        m = mn;
    }

    // ---- deterministic CTA combine (serialized per-warp, no atomics) ----
    __shared__ float sm[8], sz[8];
    __shared__ float sacc[HH];
    if (lane == 0) { sm[w] = m; sz[w] = z; }
    __syncthreads();
    float mc = sm[0];
#pragma unroll
    for (int i = 1; i < 8; i++) mc = fmaxf(mc, sm[i]);
    float scale = __expf(m - mc);

    for (int i = tid; i < HH; i += 256) sacc[i] = 0.f;
    __syncthreads();
    for (int ww = 0; ww < 8; ww++) {
        if (w == ww) {
#pragma unroll
            for (int j = 0; j < 8; j++) {
                int h = j * 128 + lane * 4;
                sacc[h + 0] += a4[j].x * scale;
                sacc[h + 1] += a4[j].y * scale;
                sacc[h + 2] += a4[j].z * scale;
                sacc[h + 3] += a4[j].w * scale;
            }
        }
        __syncthreads();
    }
    float zc = 0.f;
#pragma unroll
    for (int i = 0; i < 8; i++) zc += sz[i] * __expf(sm[i] - mc);

    float* rec = g_part + (size_t)blk * REC;
    for (int i = tid; i < HH; i += 256) rec[i] = sacc[i];
    if (tid == 0) { rec[HH] = mc; rec[HH + 1] = zc; }
}

// ---------------- K2: merge chunk partials per b ----------------
__global__ void k_combine()
{
    int b = blockIdx.x;
    int tid = threadIdx.x;
    __shared__ float cscale[CHUNKS];

    float mb = -3.0e38f;
    for (int c = 0; c < CHUNKS; c++)
        mb = fmaxf(mb, g_part[(size_t)(b * CHUNKS + c) * REC + HH]);
    float zb = 0.f;
    for (int c = 0; c < CHUNKS; c++) {
        const float* rec = g_part + (size_t)(b * CHUNKS + c) * REC;
        zb += rec[HH + 1] * __expf(rec[HH] - mb);
    }
    if (tid < CHUNKS) {
        const float* rec = g_part + (size_t)(b * CHUNKS + tid) * REC;
        cscale[tid] = __expf(rec[HH] - mb);
    }
    __syncthreads();

    float inv = 1.f / zb;
    for (int h = tid; h < HH; h += 256) {
        float acc = 0.f;
#pragma unroll
        for (int c = 0; c < CHUNKS; c++)
            acc += g_part[(size_t)(b * CHUNKS + c) * REC + h] * cscale[c];
        g_attn[(size_t)b * HH + h] = acc * inv;
    }
    if (tid == 0) { g_mz[b * 2] = mb; g_mz[b * 2 + 1] = zb; }
}

// ---------------- K3: normalize raw scores -> At (in place in d_out) ----------------
__global__ void k_at(float* __restrict__ at)
{
    int idx = blockIdx.x * 256 + threadIdx.x;   // B*S total
    int b = idx / SS;
    float mb = g_mz[b * 2];
    float zb = g_mz[b * 2 + 1];
    at[idx] = __expf(at[idx] - mb) / zb;
}

// ---------------- GEMM: C[64 x 1024] += A[64 x K] * W[1024 x K]^T (k-split) ----------------
// grid = (16 i-tiles, KSPLIT), block = 256. Each block: 64b x 64i tile over 256 k.
// A is concat(A1[b, 0:1024], A2[b, 0:1024]) when wstride==2048.
__global__ __launch_bounds__(256) void k_gemm(
    const float* __restrict__ A1, const float* __restrict__ A2,
    const float* __restrict__ W, int wstride, float* __restrict__ outp)
{
    __shared__ float As[16][68];
    __shared__ float Ws[16][68];
    int i0 = blockIdx.x * 64;
    int k0 = blockIdx.y * 256;
    int tid = threadIdx.x;
    int tb = tid & 15, ti = tid >> 4;

    float acc[4][4];
#pragma unroll
    for (int a = 0; a < 4; a++)
#pragma unroll
        for (int c = 0; c < 4; c++) acc[a][c] = 0.f;

    for (int kk = 0; kk < 256; kk += 16) {
        int kbase = k0 + kk;
#pragma unroll
        for (int r = 0; r < 4; r++) {
            int e = tid + r * 256;        // 0..1023
            int idx6 = e >> 4;            // 0..63
            int kt = e & 15;
            int k = kbase + kt;
            // A tile: As[kt][b]
            float av = (k < HH) ? A1[(size_t)idx6 * HH + k]
                                : A2[(size_t)idx6 * HH + (k - HH)];
            As[kt][idx6] = av;
            // W tile: Ws[kt][i]
            Ws[kt][idx6] = W[(size_t)(i0 + idx6) * wstride + k];
        }
        __syncthreads();
#pragma unroll
        for (int kt = 0; kt < 16; kt++) {
            float4 av = *(const float4*)&As[kt][tb * 4];
            float4 wv = *(const float4*)&Ws[kt][ti * 4];
            acc[0][0] += av.x * wv.x; acc[0][1] += av.x * wv.y; acc[0][2] += av.x * wv.z; acc[0][3] += av.x * wv.w;
            acc[1][0] += av.y * wv.x; acc[1][1] += av.y * wv.y; acc[1][2] += av.y * wv.z; acc[1][3] += av.y * wv.w;
            acc[2][0] += av.z * wv.x; acc[2][1] += av.z * wv.y; acc[2][2] += av.z * wv.z; acc[2][3] += av.z * wv.w;
            acc[3][0] += av.w * wv.x; acc[3][1] += av.w * wv.y; acc[3][2] += av.w * wv.z; acc[3][3] += av.w * wv.w;
        }
        __syncthreads();
    }

    float* op = outp + (size_t)blockIdx.y * BB * HH;
#pragma unroll
    for (int cb = 0; cb < 4; cb++) {
        int b = tb * 4 + cb;
#pragma unroll
        for (int ci = 0; ci < 4; ci++) {
            int i = i0 + ti * 4 + ci;
            op[(size_t)b * HH + i] = acc[cb][ci];
        }
    }
}

// ---------------- reduce k-split partials + bias ----------------
__global__ void k_red(const float* __restrict__ bias, const float* __restrict__ parts,
                      int nsplit, float* __restrict__ out)
{
    int idx = blockIdx.x * 256 + threadIdx.x;   // B*H
    int i = idx & (HH - 1);
    float v = bias[i];
    for (int p = 0; p < nsplit; p++) v += parts[(size_t)p * BB * HH + idx];
    out[idx] = v;
}

// ---------------- BatchNorm (training stats, biased var) + tanh ----------------
__global__ void k_bn(const float* __restrict__ gamma, const float* __restrict__ beta)
{
    __shared__ float tile[64][65];
    __shared__ float smean[64], srstd[64];
    int i0 = blockIdx.x * 64;
    int tid = threadIdx.x;
    int ic = tid & 63, rr = tid >> 6;

    for (int b = rr; b < 64; b += 4)
        tile[b][ic] = g_x1[(size_t)b * HH + i0 + ic];
    __syncthreads();

    if (tid < 64) {
        float s = 0.f;
        for (int b = 0; b < 64; b++) s += tile[b][tid];
        float mean = s * (1.f / 64.f);
        float v = 0.f;
        for (int b = 0; b < 64; b++) { float d = tile[b][tid] - mean; v += d * d; }
        v *= (1.f / 64.f);
        smean[tid] = mean;
        srstd[tid] = rsqrtf(v + 1e-5f);
    }
    __syncthreads();

    float g = gamma[i0 + ic], be = beta[i0 + ic];
    for (int b = rr; b < 64; b += 4) {
        float x = (tile[b][ic] - smean[ic]) * srstd[ic] * g + be;
        g_x2[(size_t)b * HH + i0 + ic] = tanhf(x);
    }
}

// ---------------- launch ----------------
extern "C" void kernel_launch(void* const* d_in, const int* in_sizes, int n_in,
                              void* d_out, int out_size)
{
    const float* ctx   = (const float*)d_in[0];
    const float* key   = (const float*)d_in[1];
    const float* mask  = (const float*)d_in[2];
    const float* fc1_w = (const float*)d_in[3];
    const float* fc1_b = (const float*)d_in[4];
    const float* bn_g  = (const float*)d_in[5];
    const float* bn_b  = (const float*)d_in[6];
    const float* fc2_w = (const float*)d_in[7];
    const float* fc2_b = (const float*)d_in[8];

    float* out_x  = (float*)d_out;                 // (B, H)
    float* out_at = (float*)d_out + BB * HH;       // (B, S)

    float *p_x1p, *p_x1, *p_x3p, *p_attn, *p_x2;
    cudaGetSymbolAddress((void**)&p_x1p, g_x1p);
    cudaGetSymbolAddress((void**)&p_x1,  g_x1);
    cudaGetSymbolAddress((void**)&p_x3p, g_x3p);
    cudaGetSymbolAddress((void**)&p_attn, g_attn);
    cudaGetSymbolAddress((void**)&p_x2,  g_x2);

    // 1) fused scores + online softmax weighted sum (single pass over ctx)
    k_attn_partial<<<NBLK1, 256>>>(ctx, key, mask, out_at);
    // 2) merge chunk partials -> g_attn, g_mz
    k_combine<<<BB, 256>>>();
    // 3) normalize raw scores -> At
    k_at<<<(BB * SS) / 256, 256>>>(out_at);
    // 4) fc1: [attn | key] @ fc1_w^T   (K=2048, ksplit=8)
    k_gemm<<<dim3(16, 8), 256>>>(p_attn, key, fc1_w, 2 * HH, p_x1p);
    k_red<<<(BB * HH) / 256, 256>>>(fc1_b, p_x1p, 8, p_x1);
    // 5) batchnorm + tanh
    k_bn<<<HH / 64, 256>>>(bn_g, bn_b);
    // 6) fc2 (K=1024, ksplit=4)
    k_gemm<<<dim3(16, 4), 256>>>(p_x2, p_x2, fc2_w, HH, p_x3p);
    k_red<<<(BB * HH) / 256, 256>>>(fc2_b, p_x3p, 4, out_x);
}

// round 4
// speedup vs baseline: 1.0140x; 1.0140x over previous
#include <cuda_runtime.h>
#include <math.h>
#include <math_constants.h>

#define SS 2048
#define BB 64
#define HH 1024
#define CH 128
#define CHUNKS (SS/CH)          // 16
#define NBLK1 (BB*CHUNKS)       // 1024
#define REC 1040                // 1024 acc + m + z (padded)
#define NSPLIT 16

// ---------------- scratch (no allocations allowed) ----------------
__device__ float g_part[NBLK1 * REC];        // ~4.3 MB partial softmax records
__device__ float g_attn[BB * HH];            // attention-pooled context
__device__ float g_x1p[NSPLIT * BB * HH];    // gemm1 k-split partials (4 MB)
__device__ float g_x2[BB * HH];              // bn+tanh output
__device__ float g_x3p[NSPLIT * BB * HH];    // gemm2 k-split partials (4 MB)

// ---------------- K1: fused scores + online-softmax weighted sum ----------------
// grid = 1024 (b * 16 chunks), block = 256 (8 warps). Each warp processes 16 rows,
// keeps key and a full-H accumulator in registers (h = j*128 + lane*4 + c).
__global__ __launch_bounds__(256, 2) void k_attn_partial(
    const float* __restrict__ ctx, const float* __restrict__ key,
    const float* __restrict__ mask, float* __restrict__ scores_raw)
{
    int blk = blockIdx.x;
    int b = blk / CHUNKS;
    int chunk = blk % CHUNKS;
    int s0 = chunk * CH;
    int tid = threadIdx.x;
    int w = tid >> 5;
    int lane = tid & 31;

    const float4* keyv = (const float4*)(key + (size_t)b * HH);
    float4 k4[8];
#pragma unroll
    for (int j = 0; j < 8; j++) k4[j] = keyv[j * 32 + lane];

    float4 a4[8];
#pragma unroll
    for (int j = 0; j < 8; j++) a4[j] = make_float4(0.f, 0.f, 0.f, 0.f);
    float m = -3.0e38f, z = 0.f;

    for (int t = 0; t < CH / 8; t++) {
        int s = s0 + w + t * 8;
        const float4* row = (const float4*)(ctx + ((size_t)s * BB + b) * HH);
        float4 r4[8];
#pragma unroll
        for (int j = 0; j < 8; j++) r4[j] = row[j * 32 + lane];

        float p = 0.f;
#pragma unroll
        for (int j = 0; j < 8; j++)
            p += r4[j].x * k4[j].x + r4[j].y * k4[j].y + r4[j].z * k4[j].z + r4[j].w * k4[j].w;
#pragma unroll
        for (int off = 16; off > 0; off >>= 1)
            p += __shfl_xor_sync(0xffffffffu, p, off);

        float score = p + mask[(size_t)b * SS + s];
        if (lane == 0) scores_raw[(size_t)b * SS + s] = score;

        float mn = fmaxf(m, score);
        float alpha = __expf(m - mn);
        float pe = __expf(score - mn);
        z = z * alpha + pe;
#pragma unroll
        for (int j = 0; j < 8; j++) {
            a4[j].x = a4[j].x * alpha + pe * r4[j].x;
            a4[j].y = a4[j].y * alpha + pe * r4[j].y;
            a4[j].z = a4[j].z * alpha + pe * r4[j].z;
            a4[j].w = a4[j].w * alpha + pe * r4[j].w;
        }
        m = mn;
    }

    // ---- deterministic CTA combine (serialized per-warp, no atomics) ----
    __shared__ float sm[8], sz[8];
    __shared__ float sacc[HH];
    if (lane == 0) { sm[w] = m; sz[w] = z; }
    __syncthreads();
    float mc = sm[0];
#pragma unroll
    for (int i = 1; i < 8; i++) mc = fmaxf(mc, sm[i]);
    float scale = __expf(m - mc);

    for (int i = tid; i < HH; i += 256) sacc[i] = 0.f;
    __syncthreads();
    for (int ww = 0; ww < 8; ww++) {
        if (w == ww) {
#pragma unroll
            for (int j = 0; j < 8; j++) {
                int h = j * 128 + lane * 4;
                sacc[h + 0] += a4[j].x * scale;
                sacc[h + 1] += a4[j].y * scale;
                sacc[h + 2] += a4[j].z * scale;
                sacc[h + 3] += a4[j].w * scale;
            }
        }
        __syncthreads();
    }
    float zc = 0.f;
#pragma unroll
    for (int i = 0; i < 8; i++) zc += sz[i] * __expf(sm[i] - mc);

    float* rec = g_part + (size_t)blk * REC;
    for (int i = tid; i < HH; i += 256) rec[i] = sacc[i];
    if (tid == 0) { rec[HH] = mc; rec[HH + 1] = zc; }
}

// ---------------- K2: merge chunk partials per b + normalize At ----------------
__global__ void k_combine(float* __restrict__ at)
{
    int b = blockIdx.x;
    int tid = threadIdx.x;
    __shared__ float cscale[CHUNKS];

    float mb = -3.0e38f;
    for (int c = 0; c < CHUNKS; c++)
        mb = fmaxf(mb, g_part[(size_t)(b * CHUNKS + c) * REC + HH]);
    float zb = 0.f;
    for (int c = 0; c < CHUNKS; c++) {
        const float* rec = g_part + (size_t)(b * CHUNKS + c) * REC;
        zb += rec[HH + 1] * __expf(rec[HH] - mb);
    }
    if (tid < CHUNKS) {
        const float* rec = g_part + (size_t)(b * CHUNKS + tid) * REC;
        cscale[tid] = __expf(rec[HH] - mb);
    }
    __syncthreads();

    float inv = 1.f / zb;
    for (int h = tid; h < HH; h += 256) {
        float acc = 0.f;
#pragma unroll
        for (int c = 0; c < CHUNKS; c++)
            acc += g_part[(size_t)(b * CHUNKS + c) * REC + h] * cscale[c];
        g_attn[(size_t)b * HH + h] = acc * inv;
    }
    // fused: normalize raw scores -> At
    for (int s = tid; s < SS; s += 256) {
        size_t idx = (size_t)b * SS + s;
        at[idx] = __expf(at[idx] - mb) * inv;
    }
}

// ---------------- GEMM: C[64 x 1024] = A[64 x K] * W[1024 x K]^T (k-split) ----------------
// grid = (16 i-tiles, 16 ksplit), block = 256. Double-buffered via register prefetch.
// A is concat(A1[b,0:1024], A2[b,0:1024]) when wstride==2048.
__global__ __launch_bounds__(256) void k_gemm(
    const float* __restrict__ A1, const float* __restrict__ A2,
    const float* __restrict__ W, int wstride, int kchunk, float* __restrict__ outp)
{
    __shared__ float As[16][68];
    __shared__ float Ws[16][68];
    int i0 = blockIdx.x * 64;
    int k0 = blockIdx.y * kchunk;
    int tid = threadIdx.x;
    int tb = tid & 15, ti = tid >> 4;
    int row = tid >> 2;            // 0..63
    int kq  = (tid & 3) * 4;       // 0,4,8,12
    int niter = kchunk >> 4;

    float4 pa, pw;
    {
        int k = k0 + kq;
        const float* ap = (k < HH) ? (A1 + (size_t)row * HH + k)
                                   : (A2 + (size_t)row * HH + (k - HH));
        pa = *(const float4*)ap;
        pw = *(const float4*)(W + (size_t)(i0 + row) * wstride + k);
    }

    float acc[4][4];
#pragma unroll
    for (int a = 0; a < 4; a++)
#pragma unroll
        for (int c = 0; c < 4; c++) acc[a][c] = 0.f;

    for (int kk = 0; kk < niter; kk++) {
        As[kq + 0][row] = pa.x; As[kq + 1][row] = pa.y;
        As[kq + 2][row] = pa.z; As[kq + 3][row] = pa.w;
        Ws[kq + 0][row] = pw.x; Ws[kq + 1][row] = pw.y;
        Ws[kq + 2][row] = pw.z; Ws[kq + 3][row] = pw.w;
        __syncthreads();

        if (kk + 1 < niter) {
            int k = k0 + (kk + 1) * 16 + kq;
            const float* ap = (k < HH) ? (A1 + (size_t)row * HH + k)
                                       : (A2 + (size_t)row * HH + (k - HH));
            pa = *(const float4*)ap;
            pw = *(const float4*)(W + (size_t)(i0 + row) * wstride + k);
        }

#pragma unroll
        for (int kt = 0; kt < 16; kt++) {
            float4 av = *(const float4*)&As[kt][tb * 4];
            float4 wv = *(const float4*)&Ws[kt][ti * 4];
            acc[0][0] += av.x * wv.x; acc[0][1] += av.x * wv.y; acc[0][2] += av.x * wv.z; acc[0][3] += av.x * wv.w;
            acc[1][0] += av.y * wv.x; acc[1][1] += av.y * wv.y; acc[1][2] += av.y * wv.z; acc[1][3] += av.y * wv.w;
            acc[2][0] += av.z * wv.x; acc[2][1] += av.z * wv.y; acc[2][2] += av.z * wv.z; acc[2][3] += av.z * wv.w;
            acc[3][0] += av.w * wv.x; acc[3][1] += av.w * wv.y; acc[3][2] += av.w * wv.z; acc[3][3] += av.w * wv.w;
        }
        __syncthreads();
    }

    float* op = outp + (size_t)blockIdx.y * BB * HH;
#pragma unroll
    for (int cb = 0; cb < 4; cb++) {
        int b = tb * 4 + cb;
#pragma unroll
        for (int ci = 0; ci < 4; ci++) {
            int i = i0 + ti * 4 + ci;
            op[(size_t)b * HH + i] = acc[cb][ci];
        }
    }
}

// ---------------- fused: reduce fc1 partials + bias + BatchNorm + tanh ----------------
// grid = 16 (64 features each), block = 256. Thread owns feature ic, 16 batch rows.
__global__ void k_red_bn(const float* __restrict__ bias, const float* __restrict__ gamma,
                         const float* __restrict__ beta)
{
    int i0 = blockIdx.x * 64;
    int tid = threadIdx.x;
    int ic = tid & 63;
    int rg = tid >> 6;            // 0..3
    int i = i0 + ic;

    float v[16];
    float bi = bias[i];
#pragma unroll
    for (int j = 0; j < 16; j++) {
        int b = rg * 16 + j;
        float s = bi;
#pragma unroll
        for (int p = 0; p < NSPLIT; p++)
            s += g_x1p[(size_t)p * BB * HH + (size_t)b * HH + i];
        v[j] = s;
    }

    __shared__ float red[4][64];
    float s1 = 0.f;
#pragma unroll
    for (int j = 0; j < 16; j++) s1 += v[j];
    red[rg][ic] = s1;
    __syncthreads();
    float mean = (red[0][ic] + red[1][ic] + red[2][ic] + red[3][ic]) * (1.f / 64.f);
    __syncthreads();

    float s2 = 0.f;
#pragma unroll
    for (int j = 0; j < 16; j++) { float d = v[j] - mean; s2 += d * d; }
    red[rg][ic] = s2;
    __syncthreads();
    float var = (red[0][ic] + red[1][ic] + red[2][ic] + red[3][ic]) * (1.f / 64.f);
    float rstd = rsqrtf(var + 1e-5f);

    float g = gamma[i], be = beta[i];
#pragma unroll
    for (int j = 0; j < 16; j++) {
        int b = rg * 16 + j;
        float x = (v[j] - mean) * rstd * g + be;
        g_x2[(size_t)b * HH + i] = tanhf(x);
    }
}

// ---------------- reduce fc2 partials + bias -> final x ----------------
__global__ void k_red(const float* __restrict__ bias, const float* __restrict__ parts,
                      float* __restrict__ out)
{
    int idx = blockIdx.x * 256 + threadIdx.x;   // B*H
    int i = idx & (HH - 1);
    float v = bias[i];
#pragma unroll
    for (int p = 0; p < NSPLIT; p++) v += parts[(size_t)p * BB * HH + idx];
    out[idx] = v;
}

// ---------------- launch ----------------
extern "C" void kernel_launch(void* const* d_in, const int* in_sizes, int n_in,
                              void* d_out, int out_size)
{
    const float* ctx   = (const float*)d_in[0];
    const float* key   = (const float*)d_in[1];
    const float* mask  = (const float*)d_in[2];
    const float* fc1_w = (const float*)d_in[3];
    const float* fc1_b = (const float*)d_in[4];
    const float* bn_g  = (const float*)d_in[5];
    const float* bn_b  = (const float*)d_in[6];
    const float* fc2_w = (const float*)d_in[7];
    const float* fc2_b = (const float*)d_in[8];

    float* out_x  = (float*)d_out;                 // (B, H)
    float* out_at = (float*)d_out + BB * HH;       // (B, S)

    float *p_x1p, *p_x3p, *p_attn, *p_x2;
    cudaGetSymbolAddress((void**)&p_x1p, g_x1p);
    cudaGetSymbolAddress((void**)&p_x3p, g_x3p);
    cudaGetSymbolAddress((void**)&p_attn, g_attn);
    cudaGetSymbolAddress((void**)&p_x2,  g_x2);

    // 1) fused scores + online softmax weighted sum (single pass over ctx)
    k_attn_partial<<<NBLK1, 256>>>(ctx, key, mask, out_at);
    // 2) merge chunk partials -> g_attn, and normalize At in place
    k_combine<<<BB, 256>>>(out_at);
    // 3) fc1: [attn | key] @ fc1_w^T   (K=2048, ksplit=16, kchunk=128)
    k_gemm<<<dim3(16, NSPLIT), 256>>>(p_attn, key, fc1_w, 2 * HH, 128, p_x1p);
    // 4) reduce + bias + batchnorm + tanh (fused)
    k_red_bn<<<HH / 64, 256>>>(fc1_b, bn_g, bn_b);
    // 5) fc2 (K=1024, ksplit=16, kchunk=64)
    k_gemm<<<dim3(16, NSPLIT), 256>>>(p_x2, p_x2, fc2_w, HH, 64, p_x3p);
    // 6) reduce + bias -> out
    k_red<<<(BB * HH) / 256, 256>>>(fc2_b, p_x3p, out_x);
}

// round 5
// speedup vs baseline: 1.1281x; 1.1125x over previous
#include <cuda_runtime.h>
#include <math.h>
#include <math_constants.h>

#define SS 2048
#define BB 64
#define HH 1024
#define CH 128
#define CHUNKS (SS/CH)          // 16
#define NBLK1 (BB*CHUNKS)       // 1024
#define REC 1040                // 1024 acc + m + z (padded)
#define NSPLIT 16

// ---------------- scratch (no allocations allowed) ----------------
__device__ float g_part[NBLK1 * REC];        // ~4.3 MB partial softmax records
__device__ float g_attn[BB * HH];            // attention-pooled context
__device__ float g_x1[BB * HH];              // fc1 output (post bias)
__device__ float g_x1p[NSPLIT * BB * HH];    // gemm1 k-split partials (4 MB)
__device__ float g_x2[BB * HH];              // bn+tanh output
__device__ float g_x3p[NSPLIT * BB * HH];    // gemm2 k-split partials (4 MB)

// ---------------- K1: fused scores + online-softmax weighted sum ----------------
__global__ __launch_bounds__(256, 2) void k_attn_partial(
    const float* __restrict__ ctx, const float* __restrict__ key,
    const float* __restrict__ mask, float* __restrict__ scores_raw)
{
    int blk = blockIdx.x;
    int b = blk / CHUNKS;
    int chunk = blk % CHUNKS;
    int s0 = chunk * CH;
    int tid = threadIdx.x;
    int w = tid >> 5;
    int lane = tid & 31;

    const float4* keyv = (const float4*)(key + (size_t)b * HH);
    float4 k4[8];
#pragma unroll
    for (int j = 0; j < 8; j++) k4[j] = keyv[j * 32 + lane];

    float4 a4[8];
#pragma unroll
    for (int j = 0; j < 8; j++) a4[j] = make_float4(0.f, 0.f, 0.f, 0.f);
    float m = -3.0e38f, z = 0.f;

    for (int t = 0; t < CH / 8; t++) {
        int s = s0 + w + t * 8;
        const float4* row = (const float4*)(ctx + ((size_t)s * BB + b) * HH);
        float4 r4[8];
#pragma unroll
        for (int j = 0; j < 8; j++) r4[j] = row[j * 32 + lane];

        float p = 0.f;
#pragma unroll
        for (int j = 0; j < 8; j++)
            p += r4[j].x * k4[j].x + r4[j].y * k4[j].y + r4[j].z * k4[j].z + r4[j].w * k4[j].w;
#pragma unroll
        for (int off = 16; off > 0; off >>= 1)
            p += __shfl_xor_sync(0xffffffffu, p, off);

        float score = p + mask[(size_t)b * SS + s];
        if (lane == 0) scores_raw[(size_t)b * SS + s] = score;

        float mn = fmaxf(m, score);
        float alpha = __expf(m - mn);
        float pe = __expf(score - mn);
        z = z * alpha + pe;
#pragma unroll
        for (int j = 0; j < 8; j++) {
            a4[j].x = a4[j].x * alpha + pe * r4[j].x;
            a4[j].y = a4[j].y * alpha + pe * r4[j].y;
            a4[j].z = a4[j].z * alpha + pe * r4[j].z;
            a4[j].w = a4[j].w * alpha + pe * r4[j].w;
        }
        m = mn;
    }

    // ---- deterministic CTA combine (serialized per-warp, no atomics) ----
    __shared__ float sm[8], sz[8];
    __shared__ float sacc[HH];
    if (lane == 0) { sm[w] = m; sz[w] = z; }
    __syncthreads();
    float mc = sm[0];
#pragma unroll
    for (int i = 1; i < 8; i++) mc = fmaxf(mc, sm[i]);
    float scale = __expf(m - mc);

    for (int i = tid; i < HH; i += 256) sacc[i] = 0.f;
    __syncthreads();
    for (int ww = 0; ww < 8; ww++) {
        if (w == ww) {
#pragma unroll
            for (int j = 0; j < 8; j++) {
                int h = j * 128 + lane * 4;
                sacc[h + 0] += a4[j].x * scale;
                sacc[h + 1] += a4[j].y * scale;
                sacc[h + 2] += a4[j].z * scale;
                sacc[h + 3] += a4[j].w * scale;
            }
        }
        __syncthreads();
    }
    float zc = 0.f;
#pragma unroll
    for (int i = 0; i < 8; i++) zc += sz[i] * __expf(sm[i] - mc);

    float* rec = g_part + (size_t)blk * REC;
    for (int i = tid; i < HH; i += 256) rec[i] = sacc[i];
    if (tid == 0) { rec[HH] = mc; rec[HH + 1] = zc; }
}

// ---------------- K2: merge chunk partials per b + normalize At ----------------
__global__ void k_combine(float* __restrict__ at)
{
    int b = blockIdx.x;
    int tid = threadIdx.x;
    __shared__ float cscale[CHUNKS];

    float mb = -3.0e38f;
    for (int c = 0; c < CHUNKS; c++)
        mb = fmaxf(mb, g_part[(size_t)(b * CHUNKS + c) * REC + HH]);
    float zb = 0.f;
    for (int c = 0; c < CHUNKS; c++) {
        const float* rec = g_part + (size_t)(b * CHUNKS + c) * REC;
        zb += rec[HH + 1] * __expf(rec[HH] - mb);
    }
    if (tid < CHUNKS) {
        const float* rec = g_part + (size_t)(b * CHUNKS + tid) * REC;
        cscale[tid] = __expf(rec[HH] - mb);
    }
    __syncthreads();

    float inv = 1.f / zb;
    for (int h = tid; h < HH; h += 256) {
        float acc = 0.f;
#pragma unroll
        for (int c = 0; c < CHUNKS; c++)
            acc += g_part[(size_t)(b * CHUNKS + c) * REC + h] * cscale[c];
        g_attn[(size_t)b * HH + h] = acc * inv;
    }
    // fused: normalize raw scores -> At
    for (int s = tid; s < SS; s += 256) {
        size_t idx = (size_t)b * SS + s;
        at[idx] = __expf(at[idx] - mb) * inv;
    }
}

// ---------------- GEMM: C[64 x 1024] = A[64 x K] * W[1024 x K]^T (k-split) ----------------
__global__ __launch_bounds__(256) void k_gemm(
    const float* __restrict__ A1, const float* __restrict__ A2,
    const float* __restrict__ W, int wstride, int kchunk, float* __restrict__ outp)
{
    __shared__ float As[16][68];
    __shared__ float Ws[16][68];
    int i0 = blockIdx.x * 64;
    int k0 = blockIdx.y * kchunk;
    int tid = threadIdx.x;
    int tb = tid & 15, ti = tid >> 4;
    int row = tid >> 2;            // 0..63
    int kq  = (tid & 3) * 4;       // 0,4,8,12
    int niter = kchunk >> 4;

    float4 pa, pw;
    {
        int k = k0 + kq;
        const float* ap = (k < HH) ? (A1 + (size_t)row * HH + k)
                                   : (A2 + (size_t)row * HH + (k - HH));
        pa = *(const float4*)ap;
        pw = *(const float4*)(W + (size_t)(i0 + row) * wstride + k);
    }

    float acc[4][4];
#pragma unroll
    for (int a = 0; a < 4; a++)
#pragma unroll
        for (int c = 0; c < 4; c++) acc[a][c] = 0.f;

    for (int kk = 0; kk < niter; kk++) {
        As[kq + 0][row] = pa.x; As[kq + 1][row] = pa.y;
        As[kq + 2][row] = pa.z; As[kq + 3][row] = pa.w;
        Ws[kq + 0][row] = pw.x; Ws[kq + 1][row] = pw.y;
        Ws[kq + 2][row] = pw.z; Ws[kq + 3][row] = pw.w;
        __syncthreads();

        if (kk + 1 < niter) {
            int k = k0 + (kk + 1) * 16 + kq;
            const float* ap = (k < HH) ? (A1 + (size_t)row * HH + k)
                                       : (A2 + (size_t)row * HH + (k - HH));
            pa = *(const float4*)ap;
            pw = *(const float4*)(W + (size_t)(i0 + row) * wstride + k);
        }

#pragma unroll
        for (int kt = 0; kt < 16; kt++) {
            float4 av = *(const float4*)&As[kt][tb * 4];
            float4 wv = *(const float4*)&Ws[kt][ti * 4];
            acc[0][0] += av.x * wv.x; acc[0][1] += av.x * wv.y; acc[0][2] += av.x * wv.z; acc[0][3] += av.x * wv.w;
            acc[1][0] += av.y * wv.x; acc[1][1] += av.y * wv.y; acc[1][2] += av.y * wv.z; acc[1][3] += av.y * wv.w;
            acc[2][0] += av.z * wv.x; acc[2][1] += av.z * wv.y; acc[2][2] += av.z * wv.z; acc[2][3] += av.z * wv.w;
            acc[3][0] += av.w * wv.x; acc[3][1] += av.w * wv.y; acc[3][2] += av.w * wv.z; acc[3][3] += av.w * wv.w;
        }
        __syncthreads();
    }

    float* op = outp + (size_t)blockIdx.y * BB * HH;
#pragma unroll
    for (int cb = 0; cb < 4; cb++) {
        int b = tb * 4 + cb;
#pragma unroll
        for (int ci = 0; ci < 4; ci++) {
            int i = i0 + ti * 4 + ci;
            op[(size_t)b * HH + i] = acc[cb][ci];
        }
    }
}

// ---------------- reduce k-split partials + bias (full-chip parallel) ----------------
__global__ void k_red(const float* __restrict__ bias, const float* __restrict__ parts,
                      float* __restrict__ out)
{
    int idx = blockIdx.x * 256 + threadIdx.x;   // B*H
    int i = idx & (HH - 1);
    float v = bias[i];
#pragma unroll
    for (int p = 0; p < NSPLIT; p++) v += parts[(size_t)p * BB * HH + idx];
    out[idx] = v;
}

// ---------------- BatchNorm (training stats, biased var) + tanh ----------------
// grid = 16 (64 features each), block = 256. Reads g_x1 (256 KB, L2-hot).
__global__ void k_bn(const float* __restrict__ gamma, const float* __restrict__ beta)
{
    int i0 = blockIdx.x * 64;
    int tid = threadIdx.x;
    int ic = tid & 63;
    int rg = tid >> 6;            // 0..3
    int i = i0 + ic;

    float v[16];
#pragma unroll
    for (int j = 0; j < 16; j++)
        v[j] = g_x1[(size_t)(rg * 16 + j) * HH + i];

    __shared__ float red[4][64];
    float s1 = 0.f;
#pragma unroll
    for (int j = 0; j < 16; j++) s1 += v[j];
    red[rg][ic] = s1;
    __syncthreads();
    float mean = (red[0][ic] + red[1][ic] + red[2][ic] + red[3][ic]) * (1.f / 64.f);
    __syncthreads();

    float s2 = 0.f;
#pragma unroll
    for (int j = 0; j < 16; j++) { float d = v[j] - mean; s2 += d * d; }
    red[rg][ic] = s2;
    __syncthreads();
    float var = (red[0][ic] + red[1][ic] + red[2][ic] + red[3][ic]) * (1.f / 64.f);
    float rstd = rsqrtf(var + 1e-5f);

    float g = gamma[i], be = beta[i];
#pragma unroll
    for (int j = 0; j < 16; j++) {
        float x = (v[j] - mean) * rstd * g + be;
        g_x2[(size_t)(rg * 16 + j) * HH + i] = tanhf(x);
    }
}

// ---------------- launch ----------------
extern "C" void kernel_launch(void* const* d_in, const int* in_sizes, int n_in,
                              void* d_out, int out_size)
{
    const float* ctx   = (const float*)d_in[0];
    const float* key   = (const float*)d_in[1];
    const float* mask  = (const float*)d_in[2];
    const float* fc1_w = (const float*)d_in[3];
    const float* fc1_b = (const float*)d_in[4];
    const float* bn_g  = (const float*)d_in[5];
    const float* bn_b  = (const float*)d_in[6];
    const float* fc2_w = (const float*)d_in[7];
    const float* fc2_b = (const float*)d_in[8];

    float* out_x  = (float*)d_out;                 // (B, H)
    float* out_at = (float*)d_out + BB * HH;       // (B, S)

    float *p_x1p, *p_x1, *p_x3p, *p_attn, *p_x2;
    cudaGetSymbolAddress((void**)&p_x1p, g_x1p);
    cudaGetSymbolAddress((void**)&p_x1,  g_x1);
    cudaGetSymbolAddress((void**)&p_x3p, g_x3p);
    cudaGetSymbolAddress((void**)&p_attn, g_attn);
    cudaGetSymbolAddress((void**)&p_x2,  g_x2);

    // 1) fused scores + online softmax weighted sum (single pass over ctx)
    k_attn_partial<<<NBLK1, 256>>>(ctx, key, mask, out_at);
    // 2) merge chunk partials -> g_attn, and normalize At in place
    k_combine<<<BB, 256>>>(out_at);
    // 3) fc1: [attn | key] @ fc1_w^T   (K=2048, ksplit=16, kchunk=128)
    k_gemm<<<dim3(16, NSPLIT), 256>>>(p_attn, key, fc1_w, 2 * HH, 128, p_x1p);
    // 4) reduce + bias (full chip)
    k_red<<<(BB * HH) / 256, 256>>>(fc1_b, p_x1p, p_x1);
    // 5) batchnorm + tanh (L2-hot)
    k_bn<<<HH / 64, 256>>>(bn_g, bn_b);
    // 6) fc2 (K=1024, ksplit=16, kchunk=64)
    k_gemm<<<dim3(16, NSPLIT), 256>>>(p_x2, p_x2, fc2_w, HH, 64, p_x3p);
    // 7) reduce + bias -> out
    k_red<<<(BB * HH) / 256, 256>>>(fc2_b, p_x3p, out_x);
}

// round 6
// speedup vs baseline: 1.1812x; 1.0471x over previous
#include <cuda_runtime.h>
#include <math.h>
#include <math_constants.h>

#define SS 2048
#define BB 64
#define HH 1024
#define CH 128
#define CHUNKS (SS/CH)          // 16
#define NBLK1 (BB*CHUNKS)       // 1024
#define REC 1040                // 1024 acc + m + z (padded)
#define NSPLIT 16

// ---------------- scratch (no allocations allowed) ----------------
__device__ float g_part[NBLK1 * REC];        // ~4.3 MB partial softmax records
__device__ float g_attn[BB * HH];            // attention-pooled context
__device__ float g_x1[BB * HH];              // fc1 output (post bias)
__device__ float g_x1p[NSPLIT * BB * HH];    // gemm1 k-split partials (4 MB)
__device__ float g_x2[BB * HH];              // bn+tanh output
__device__ float g_x3p[NSPLIT * BB * HH];    // gemm2 k-split partials (4 MB)

// ---------------- K1: fused scores + online-softmax weighted sum ----------------
__global__ __launch_bounds__(256, 2) void k_attn_partial(
    const float* __restrict__ ctx, const float* __restrict__ key,
    const float* __restrict__ mask, float* __restrict__ scores_raw)
{
    int blk = blockIdx.x;
    int b = blk / CHUNKS;
    int chunk = blk % CHUNKS;
    int s0 = chunk * CH;
    int tid = threadIdx.x;
    int w = tid >> 5;
    int lane = tid & 31;

    const float4* keyv = (const float4*)(key + (size_t)b * HH);
    float4 k4[8];
#pragma unroll
    for (int j = 0; j < 8; j++) k4[j] = keyv[j * 32 + lane];

    float4 a4[8];
#pragma unroll
    for (int j = 0; j < 8; j++) a4[j] = make_float4(0.f, 0.f, 0.f, 0.f);
    float m = -3.0e38f, z = 0.f;

    for (int t = 0; t < CH / 8; t++) {
        int s = s0 + w + t * 8;
        const float4* row = (const float4*)(ctx + ((size_t)s * BB + b) * HH);
        float4 r4[8];
#pragma unroll
        for (int j = 0; j < 8; j++) r4[j] = row[j * 32 + lane];

        float p = 0.f;
#pragma unroll
        for (int j = 0; j < 8; j++)
            p += r4[j].x * k4[j].x + r4[j].y * k4[j].y + r4[j].z * k4[j].z + r4[j].w * k4[j].w;
#pragma unroll
        for (int off = 16; off > 0; off >>= 1)
            p += __shfl_xor_sync(0xffffffffu, p, off);

        float score = p + mask[(size_t)b * SS + s];
        if (lane == 0) scores_raw[(size_t)b * SS + s] = score;

        float mn = fmaxf(m, score);
        float alpha = __expf(m - mn);
        float pe = __expf(score - mn);
        z = z * alpha + pe;
#pragma unroll
        for (int j = 0; j < 8; j++) {
            a4[j].x = a4[j].x * alpha + pe * r4[j].x;
            a4[j].y = a4[j].y * alpha + pe * r4[j].y;
            a4[j].z = a4[j].z * alpha + pe * r4[j].z;
            a4[j].w = a4[j].w * alpha + pe * r4[j].w;
        }
        m = mn;
    }

    // ---- deterministic CTA combine (serialized per-warp, no atomics) ----
    __shared__ float sm[8], sz[8];
    __shared__ float sacc[HH];
    if (lane == 0) { sm[w] = m; sz[w] = z; }
    __syncthreads();
    float mc = sm[0];
#pragma unroll
    for (int i = 1; i < 8; i++) mc = fmaxf(mc, sm[i]);
    float scale = __expf(m - mc);

    for (int i = tid; i < HH; i += 256) sacc[i] = 0.f;
    __syncthreads();
    for (int ww = 0; ww < 8; ww++) {
        if (w == ww) {
#pragma unroll
            for (int j = 0; j < 8; j++) {
                int h = j * 128 + lane * 4;
                sacc[h + 0] += a4[j].x * scale;
                sacc[h + 1] += a4[j].y * scale;
                sacc[h + 2] += a4[j].z * scale;
                sacc[h + 3] += a4[j].w * scale;
            }
        }
        __syncthreads();
    }
    float zc = 0.f;
#pragma unroll
    for (int i = 0; i < 8; i++) zc += sz[i] * __expf(sm[i] - mc);

    float* rec = g_part + (size_t)blk * REC;
    for (int i = tid; i < HH; i += 256) rec[i] = sacc[i];
    if (tid == 0) { rec[HH] = mc; rec[HH + 1] = zc; }
}

// ---------------- K2: merge chunk partials per b + normalize At (parallel) ----------------
// grid = (5, BB): x<4 -> 256-wide h slice of the weighted-sum merge; x==4 -> At row.
__global__ void k_combine(float* __restrict__ at)
{
    int part = blockIdx.x;
    int b = blockIdx.y;
    int tid = threadIdx.x;

    // every CTA recomputes mb/zb from the 32 scalars (cheap, deterministic)
    float mb = -3.0e38f;
#pragma unroll
    for (int c = 0; c < CHUNKS; c++)
        mb = fmaxf(mb, g_part[(size_t)(b * CHUNKS + c) * REC + HH]);
    float zb = 0.f;
#pragma unroll
    for (int c = 0; c < CHUNKS; c++) {
        const float* rec = g_part + (size_t)(b * CHUNKS + c) * REC;
        zb += rec[HH + 1] * __expf(rec[HH] - mb);
    }
    float inv = 1.f / zb;

    if (part < 4) {
        float cs[CHUNKS];
#pragma unroll
        for (int c = 0; c < CHUNKS; c++)
            cs[c] = __expf(g_part[(size_t)(b * CHUNKS + c) * REC + HH] - mb);
        int h = part * 256 + tid;
        float acc = 0.f;
#pragma unroll
        for (int c = 0; c < CHUNKS; c++)
            acc += g_part[(size_t)(b * CHUNKS + c) * REC + h] * cs[c];
        g_attn[(size_t)b * HH + h] = acc * inv;
    } else {
        // normalize raw scores -> At, float4 in place
        float4* atv = (float4*)(at + (size_t)b * SS);
        for (int s = tid; s < SS / 4; s += 256) {
            float4 v = atv[s];
            v.x = __expf(v.x - mb) * inv;
            v.y = __expf(v.y - mb) * inv;
            v.z = __expf(v.z - mb) * inv;
            v.w = __expf(v.w - mb) * inv;
            atv[s] = v;
        }
    }
}

// ---------------- GEMM: C[64 x 1024] = A[64 x K] * W[1024 x K]^T (k-split) ----------------
__global__ __launch_bounds__(256) void k_gemm(
    const float* __restrict__ A1, const float* __restrict__ A2,
    const float* __restrict__ W, int wstride, int kchunk, float* __restrict__ outp)
{
    __shared__ float As[16][68];
    __shared__ float Ws[16][68];
    int i0 = blockIdx.x * 64;
    int k0 = blockIdx.y * kchunk;
    int tid = threadIdx.x;
    int tb = tid & 15, ti = tid >> 4;
    int row = tid >> 2;            // 0..63
    int kq  = (tid & 3) * 4;       // 0,4,8,12
    int niter = kchunk >> 4;

    float4 pa, pw;
    {
        int k = k0 + kq;
        const float* ap = (k < HH) ? (A1 + (size_t)row * HH + k)
                                   : (A2 + (size_t)row * HH + (k - HH));
        pa = *(const float4*)ap;
        pw = *(const float4*)(W + (size_t)(i0 + row) * wstride + k);
    }

    float acc[4][4];
#pragma unroll
    for (int a = 0; a < 4; a++)
#pragma unroll
        for (int c = 0; c < 4; c++) acc[a][c] = 0.f;

    for (int kk = 0; kk < niter; kk++) {
        As[kq + 0][row] = pa.x; As[kq + 1][row] = pa.y;
        As[kq + 2][row] = pa.z; As[kq + 3][row] = pa.w;
        Ws[kq + 0][row] = pw.x; Ws[kq + 1][row] = pw.y;
        Ws[kq + 2][row] = pw.z; Ws[kq + 3][row] = pw.w;
        __syncthreads();

        if (kk + 1 < niter) {
            int k = k0 + (kk + 1) * 16 + kq;
            const float* ap = (k < HH) ? (A1 + (size_t)row * HH + k)
                                       : (A2 + (size_t)row * HH + (k - HH));
            pa = *(const float4*)ap;
            pw = *(const float4*)(W + (size_t)(i0 + row) * wstride + k);
        }

#pragma unroll
        for (int kt = 0; kt < 16; kt++) {
            float4 av = *(const float4*)&As[kt][tb * 4];
            float4 wv = *(const float4*)&Ws[kt][ti * 4];
            acc[0][0] += av.x * wv.x; acc[0][1] += av.x * wv.y; acc[0][2] += av.x * wv.z; acc[0][3] += av.x * wv.w;
            acc[1][0] += av.y * wv.x; acc[1][1] += av.y * wv.y; acc[1][2] += av.y * wv.z; acc[1][3] += av.y * wv.w;
            acc[2][0] += av.z * wv.x; acc[2][1] += av.z * wv.y; acc[2][2] += av.z * wv.z; acc[2][3] += av.z * wv.w;
            acc[3][0] += av.w * wv.x; acc[3][1] += av.w * wv.y; acc[3][2] += av.w * wv.z; acc[3][3] += av.w * wv.w;
        }
        __syncthreads();
    }

    float* op = outp + (size_t)blockIdx.y * BB * HH;
#pragma unroll
    for (int cb = 0; cb < 4; cb++) {
        int b = tb * 4 + cb;
#pragma unroll
        for (int ci = 0; ci < 4; ci++) {
            int i = i0 + ti * 4 + ci;
            op[(size_t)b * HH + i] = acc[cb][ci];
        }
    }
}

// ---------------- reduce k-split partials + bias (float4, MLP=16) ----------------
// grid = 64, block = 256; one float4 output per thread.
__global__ void k_red(const float* __restrict__ bias, const float* __restrict__ parts,
                      float* __restrict__ out)
{
    int t = blockIdx.x * 256 + threadIdx.x;     // 0..16383 float4 slots
    int i4 = (t * 4) & (HH - 1);
    float4 v = *(const float4*)(bias + i4);
#pragma unroll
    for (int p = 0; p < NSPLIT; p++) {
        float4 x = *(const float4*)(parts + (size_t)p * BB * HH + (size_t)t * 4);
        v.x += x.x; v.y += x.y; v.z += x.z; v.w += x.w;
    }
    *(float4*)(out + (size_t)t * 4) = v;
}

// ---------------- BatchNorm (training stats, biased var) + tanh ----------------
// grid = 16 (64 features each), block = 256. Reads g_x1 (256 KB, L2-hot).
__global__ void k_bn(const float* __restrict__ gamma, const float* __restrict__ beta)
{
    int i0 = blockIdx.x * 64;
    int tid = threadIdx.x;
    int ic = tid & 63;
    int rg = tid >> 6;            // 0..3
    int i = i0 + ic;

    float v[16];
#pragma unroll
    for (int j = 0; j < 16; j++)
        v[j] = g_x1[(size_t)(rg * 16 + j) * HH + i];

    __shared__ float red[4][64];
    float s1 = 0.f;
#pragma unroll
    for (int j = 0; j < 16; j++) s1 += v[j];
    red[rg][ic] = s1;
    __syncthreads();
    float mean = (red[0][ic] + red[1][ic] + red[2][ic] + red[3][ic]) * (1.f / 64.f);
    __syncthreads();

    float s2 = 0.f;
#pragma unroll
    for (int j = 0; j < 16; j++) { float d = v[j] - mean; s2 += d * d; }
    red[rg][ic] = s2;
    __syncthreads();
    float var = (red[0][ic] + red[1][ic] + red[2][ic] + red[3][ic]) * (1.f / 64.f);
    float rstd = rsqrtf(var + 1e-5f);

    float g = gamma[i], be = beta[i];
#pragma unroll
    for (int j = 0; j < 16; j++) {
        float x = (v[j] - mean) * rstd * g + be;
        g_x2[(size_t)(rg * 16 + j) * HH + i] = tanhf(x);
    }
}

// ---------------- launch ----------------
extern "C" void kernel_launch(void* const* d_in, const int* in_sizes, int n_in,
                              void* d_out, int out_size)
{
    const float* ctx   = (const float*)d_in[0];
    const float* key   = (const float*)d_in[1];
    const float* mask  = (const float*)d_in[2];
    const float* fc1_w = (const float*)d_in[3];
    const float* fc1_b = (const float*)d_in[4];
    const float* bn_g  = (const float*)d_in[5];
    const float* bn_b  = (const float*)d_in[6];
    const float* fc2_w = (const float*)d_in[7];
    const float* fc2_b = (const float*)d_in[8];

    float* out_x  = (float*)d_out;                 // (B, H)
    float* out_at = (float*)d_out + BB * HH;       // (B, S)

    float *p_x1p, *p_x1, *p_x3p, *p_attn, *p_x2;
    cudaGetSymbolAddress((void**)&p_x1p, g_x1p);
    cudaGetSymbolAddress((void**)&p_x1,  g_x1);
    cudaGetSymbolAddress((void**)&p_x3p, g_x3p);
    cudaGetSymbolAddress((void**)&p_attn, g_attn);
    cudaGetSymbolAddress((void**)&p_x2,  g_x2);

    // 1) fused scores + online softmax weighted sum (single pass over ctx)
    k_attn_partial<<<NBLK1, 256>>>(ctx, key, mask, out_at);
    // 2) merge chunk partials -> g_attn, normalize At (320 CTAs)
    k_combine<<<dim3(5, BB), 256>>>(out_at);
    // 3) fc1: [attn | key] @ fc1_w^T   (K=2048, ksplit=16, kchunk=128)
    k_gemm<<<dim3(16, NSPLIT), 256>>>(p_attn, key, fc1_w, 2 * HH, 128, p_x1p);
    // 4) reduce + bias (float4)
    k_red<<<64, 256>>>(fc1_b, p_x1p, p_x1);
    // 5) batchnorm + tanh (L2-hot)
    k_bn<<<HH / 64, 256>>>(bn_g, bn_b);
    // 6) fc2 (K=1024, ksplit=16, kchunk=64)
    k_gemm<<<dim3(16, NSPLIT), 256>>>(p_x2, p_x2, fc2_w, HH, 64, p_x3p);
    // 7) reduce + bias -> out (float4)
    k_red<<<64, 256>>>(fc2_b, p_x3p, out_x);
}

// round 7
// speedup vs baseline: 1.2708x; 1.0759x over previous
#include <cuda_runtime.h>
#include <math.h>
#include <math_constants.h>

#define SS 2048
#define BB 64
#define HH 1024
#define CH 128
#define CHUNKS (SS/CH)          // 16
#define NBLK1 (BB*CHUNKS)       // 1024
#define REC 1040                // 1024 acc + m + z (padded)
#define NSPLIT 16

// ---------------- scratch (no allocations allowed) ----------------
__device__ float g_part[NBLK1 * REC];        // ~4.3 MB partial softmax records
__device__ float g_attn[BB * HH];            // attention-pooled context
__device__ float g_x1[BB * HH];              // fc1 output (post bias)
__device__ float g_x1p[NSPLIT * BB * HH];    // gemm1 k-split partials (4 MB)
__device__ float g_x2[BB * HH];              // bn+tanh output
__device__ float g_x3p[NSPLIT * BB * HH];    // gemm2 k-split partials (4 MB)

// ---------------- K1: fused scores + online-softmax weighted sum ----------------
__global__ __launch_bounds__(256, 2) void k_attn_partial(
    const float* __restrict__ ctx, const float* __restrict__ key,
    const float* __restrict__ mask, float* __restrict__ scores_raw)
{
    int blk = blockIdx.x;
    int b = blk / CHUNKS;
    int chunk = blk % CHUNKS;
    int s0 = chunk * CH;
    int tid = threadIdx.x;
    int w = tid >> 5;
    int lane = tid & 31;

    const float4* keyv = (const float4*)(key + (size_t)b * HH);
    float4 k4[8];
#pragma unroll
    for (int j = 0; j < 8; j++) k4[j] = keyv[j * 32 + lane];

    float4 a4[8];
#pragma unroll
    for (int j = 0; j < 8; j++) a4[j] = make_float4(0.f, 0.f, 0.f, 0.f);
    float m = -3.0e38f, z = 0.f;

    for (int t = 0; t < CH / 8; t++) {
        int s = s0 + w + t * 8;
        const float4* row = (const float4*)(ctx + ((size_t)s * BB + b) * HH);
        float4 r4[8];
#pragma unroll
        for (int j = 0; j < 8; j++) r4[j] = row[j * 32 + lane];

        float p = 0.f;
#pragma unroll
        for (int j = 0; j < 8; j++)
            p += r4[j].x * k4[j].x + r4[j].y * k4[j].y + r4[j].z * k4[j].z + r4[j].w * k4[j].w;
#pragma unroll
        for (int off = 16; off > 0; off >>= 1)
            p += __shfl_xor_sync(0xffffffffu, p, off);

        float score = p + mask[(size_t)b * SS + s];
        if (lane == 0) scores_raw[(size_t)b * SS + s] = score;

        float mn = fmaxf(m, score);
        float alpha = __expf(m - mn);
        float pe = __expf(score - mn);
        z = z * alpha + pe;
#pragma unroll
        for (int j = 0; j < 8; j++) {
            a4[j].x = a4[j].x * alpha + pe * r4[j].x;
            a4[j].y = a4[j].y * alpha + pe * r4[j].y;
            a4[j].z = a4[j].z * alpha + pe * r4[j].z;
            a4[j].w = a4[j].w * alpha + pe * r4[j].w;
        }
        m = mn;
    }

    // ---- deterministic CTA combine: per-warp smem slabs + single parallel reduce ----
    __shared__ float sm[8], sz[8];
    __shared__ float sacc8[8][HH];       // 32 KB
    if (lane == 0) { sm[w] = m; sz[w] = z; }
    __syncthreads();
    float mc = sm[0];
#pragma unroll
    for (int i = 1; i < 8; i++) mc = fmaxf(mc, sm[i]);
    float scale = __expf(m - mc);

    float4* myrow = (float4*)sacc8[w];
#pragma unroll
    for (int j = 0; j < 8; j++) {
        float4 v;
        v.x = a4[j].x * scale; v.y = a4[j].y * scale;
        v.z = a4[j].z * scale; v.w = a4[j].w * scale;
        myrow[j * 32 + lane] = v;
    }
    __syncthreads();

    float zc = 0.f;
#pragma unroll
    for (int i = 0; i < 8; i++) zc += sz[i] * __expf(sm[i] - mc);

    // each thread reduces one float4 slot across the 8 warp slabs
    float* rec = g_part + (size_t)blk * REC;
    {
        float4 acc = *(float4*)&sacc8[0][tid * 4];
#pragma unroll
        for (int i = 1; i < 8; i++) {
            float4 v = *(float4*)&sacc8[i][tid * 4];
            acc.x += v.x; acc.y += v.y; acc.z += v.z; acc.w += v.w;
        }
        *(float4*)(rec + tid * 4) = acc;
    }
    if (tid == 0) { rec[HH] = mc; rec[HH + 1] = zc; }
}

// ---------------- K2: merge chunk partials per b + normalize At (parallel) ----------------
// grid = (5, BB): x<4 -> 256-wide h slice of the weighted-sum merge; x==4 -> At row.
__global__ void k_combine(float* __restrict__ at)
{
    int part = blockIdx.x;
    int b = blockIdx.y;
    int tid = threadIdx.x;

    float mb = -3.0e38f;
#pragma unroll
    for (int c = 0; c < CHUNKS; c++)
        mb = fmaxf(mb, g_part[(size_t)(b * CHUNKS + c) * REC + HH]);
    float zb = 0.f;
#pragma unroll
    for (int c = 0; c < CHUNKS; c++) {
        const float* rec = g_part + (size_t)(b * CHUNKS + c) * REC;
        zb += rec[HH + 1] * __expf(rec[HH] - mb);
    }
    float inv = 1.f / zb;

    if (part < 4) {
        float cs[CHUNKS];
#pragma unroll
        for (int c = 0; c < CHUNKS; c++)
            cs[c] = __expf(g_part[(size_t)(b * CHUNKS + c) * REC + HH] - mb);
        int h = part * 256 + tid;
        float acc = 0.f;
#pragma unroll
        for (int c = 0; c < CHUNKS; c++)
            acc += g_part[(size_t)(b * CHUNKS + c) * REC + h] * cs[c];
        g_attn[(size_t)b * HH + h] = acc * inv;
    } else {
        float4* atv = (float4*)(at + (size_t)b * SS);
        for (int s = tid; s < SS / 4; s += 256) {
            float4 v = atv[s];
            v.x = __expf(v.x - mb) * inv;
            v.y = __expf(v.y - mb) * inv;
            v.z = __expf(v.z - mb) * inv;
            v.w = __expf(v.w - mb) * inv;
            atv[s] = v;
        }
    }
}

// ---------------- GEMM: C[64 x 1024] = A[64 x K] * W[1024 x K]^T (k-split) ----------------
__global__ __launch_bounds__(256) void k_gemm(
    const float* __restrict__ A1, const float* __restrict__ A2,
    const float* __restrict__ W, int wstride, int kchunk, float* __restrict__ outp)
{
    __shared__ float As[16][68];
    __shared__ float Ws[16][68];
    int i0 = blockIdx.x * 64;
    int k0 = blockIdx.y * kchunk;
    int tid = threadIdx.x;
    int tb = tid & 15, ti = tid >> 4;
    int row = tid >> 2;            // 0..63
    int kq  = (tid & 3) * 4;       // 0,4,8,12
    int niter = kchunk >> 4;

    float4 pa, pw;
    {
        int k = k0 + kq;
        const float* ap = (k < HH) ? (A1 + (size_t)row * HH + k)
                                   : (A2 + (size_t)row * HH + (k - HH));
        pa = *(const float4*)ap;
        pw = *(const float4*)(W + (size_t)(i0 + row) * wstride + k);
    }

    float acc[4][4];
#pragma unroll
    for (int a = 0; a < 4; a++)
#pragma unroll
        for (int c = 0; c < 4; c++) acc[a][c] = 0.f;

    for (int kk = 0; kk < niter; kk++) {
        As[kq + 0][row] = pa.x; As[kq + 1][row] = pa.y;
        As[kq + 2][row] = pa.z; As[kq + 3][row] = pa.w;
        Ws[kq + 0][row] = pw.x; Ws[kq + 1][row] = pw.y;
        Ws[kq + 2][row] = pw.z; Ws[kq + 3][row] = pw.w;
        __syncthreads();

        if (kk + 1 < niter) {
            int k = k0 + (kk + 1) * 16 + kq;
            const float* ap = (k < HH) ? (A1 + (size_t)row * HH + k)
                                       : (A2 + (size_t)row * HH + (k - HH));
            pa = *(const float4*)ap;
            pw = *(const float4*)(W + (size_t)(i0 + row) * wstride + k);
        }

#pragma unroll
        for (int kt = 0; kt < 16; kt++) {
            float4 av = *(const float4*)&As[kt][tb * 4];
            float4 wv = *(const float4*)&Ws[kt][ti * 4];
            acc[0][0] += av.x * wv.x; acc[0][1] += av.x * wv.y; acc[0][2] += av.x * wv.z; acc[0][3] += av.x * wv.w;
            acc[1][0] += av.y * wv.x; acc[1][1] += av.y * wv.y; acc[1][2] += av.y * wv.z; acc[1][3] += av.y * wv.w;
            acc[2][0] += av.z * wv.x; acc[2][1] += av.z * wv.y; acc[2][2] += av.z * wv.z; acc[2][3] += av.z * wv.w;
            acc[3][0] += av.w * wv.x; acc[3][1] += av.w * wv.y; acc[3][2] += av.w * wv.z; acc[3][3] += av.w * wv.w;
        }
        __syncthreads();
    }

    float* op = outp + (size_t)blockIdx.y * BB * HH;
#pragma unroll
    for (int cb = 0; cb < 4; cb++) {
        int b = tb * 4 + cb;
#pragma unroll
        for (int ci = 0; ci < 4; ci++) {
            int i = i0 + ti * 4 + ci;
            op[(size_t)b * HH + i] = acc[cb][ci];
        }
    }
}

// ---------------- reduce k-split partials + bias (full chip, split-partial) ----------------
// grid = 256, block = 256. 4 lanes per output float4; each sums 4 partials, shfl-combine.
__global__ void k_red(const float* __restrict__ bias, const float* __restrict__ parts,
                      float* __restrict__ out)
{
    int t = blockIdx.x * 256 + threadIdx.x;   // 0..65535
    int o = t >> 2;                            // float4 slot 0..16383
    int pg = t & 3;

    float4 v = make_float4(0.f, 0.f, 0.f, 0.f);
#pragma unroll
    for (int p = 0; p < 4; p++) {
        float4 x = *(const float4*)(parts + (size_t)(pg * 4 + p) * BB * HH + (size_t)o * 4);
        v.x += x.x; v.y += x.y; v.z += x.z; v.w += x.w;
    }
#pragma unroll
    for (int off = 1; off <= 2; off <<= 1) {
        v.x += __shfl_xor_sync(0xffffffffu, v.x, off);
        v.y += __shfl_xor_sync(0xffffffffu, v.y, off);
        v.z += __shfl_xor_sync(0xffffffffu, v.z, off);
        v.w += __shfl_xor_sync(0xffffffffu, v.w, off);
    }
    if (pg == 0) {
        int i4 = (o * 4) & (HH - 1);
        float4 bv = *(const float4*)(bias + i4);
        v.x += bv.x; v.y += bv.y; v.z += bv.z; v.w += bv.w;
        *(float4*)(out + (size_t)o * 4) = v;
    }
}

// ---------------- BatchNorm (training stats, biased var) + tanh ----------------
__global__ void k_bn(const float* __restrict__ gamma, const float* __restrict__ beta)
{
    int i0 = blockIdx.x * 64;
    int tid = threadIdx.x;
    int ic = tid & 63;
    int rg = tid >> 6;            // 0..3
    int i = i0 + ic;

    float v[16];
#pragma unroll
    for (int j = 0; j < 16; j++)
        v[j] = g_x1[(size_t)(rg * 16 + j) * HH + i];

    __shared__ float red[4][64];
    float s1 = 0.f;
#pragma unroll
    for (int j = 0; j < 16; j++) s1 += v[j];
    red[rg][ic] = s1;
    __syncthreads();
    float mean = (red[0][ic] + red[1][ic] + red[2][ic] + red[3][ic]) * (1.f / 64.f);
    __syncthreads();

    float s2 = 0.f;
#pragma unroll
    for (int j = 0; j < 16; j++) { float d = v[j] - mean; s2 += d * d; }
    red[rg][ic] = s2;
    __syncthreads();
    float var = (red[0][ic] + red[1][ic] + red[2][ic] + red[3][ic]) * (1.f / 64.f);
    float rstd = rsqrtf(var + 1e-5f);

    float g = gamma[i], be = beta[i];
#pragma unroll
    for (int j = 0; j < 16; j++) {
        float x = (v[j] - mean) * rstd * g + be;
        g_x2[(size_t)(rg * 16 + j) * HH + i] = tanhf(x);
    }
}

// ---------------- launch ----------------
extern "C" void kernel_launch(void* const* d_in, const int* in_sizes, int n_in,
                              void* d_out, int out_size)
{
    const float* ctx   = (const float*)d_in[0];
    const float* key   = (const float*)d_in[1];
    const float* mask  = (const float*)d_in[2];
    const float* fc1_w = (const float*)d_in[3];
    const float* fc1_b = (const float*)d_in[4];
    const float* bn_g  = (const float*)d_in[5];
    const float* bn_b  = (const float*)d_in[6];
    const float* fc2_w = (const float*)d_in[7];
    const float* fc2_b = (const float*)d_in[8];

    float* out_x  = (float*)d_out;                 // (B, H)
    float* out_at = (float*)d_out + BB * HH;       // (B, S)

    float *p_x1p, *p_x1, *p_x3p, *p_attn, *p_x2;
    cudaGetSymbolAddress((void**)&p_x1p, g_x1p);
    cudaGetSymbolAddress((void**)&p_x1,  g_x1);
    cudaGetSymbolAddress((void**)&p_x3p, g_x3p);
    cudaGetSymbolAddress((void**)&p_attn, g_attn);
    cudaGetSymbolAddress((void**)&p_x2,  g_x2);

    // 1) fused scores + online softmax weighted sum (single pass over ctx)
    k_attn_partial<<<NBLK1, 256>>>(ctx, key, mask, out_at);
    // 2) merge chunk partials -> g_attn, normalize At (320 CTAs)
    k_combine<<<dim3(5, BB), 256>>>(out_at);
    // 3) fc1: [attn | key] @ fc1_w^T   (K=2048, ksplit=16, kchunk=128)
    k_gemm<<<dim3(16, NSPLIT), 256>>>(p_attn, key, fc1_w, 2 * HH, 128, p_x1p);
    // 4) reduce + bias (full chip, split-partial)
    k_red<<<256, 256>>>(fc1_b, p_x1p, p_x1);
    // 5) batchnorm + tanh (L2-hot)
    k_bn<<<HH / 64, 256>>>(bn_g, bn_b);
    // 6) fc2 (K=1024, ksplit=16, kchunk=64)
    k_gemm<<<dim3(16, NSPLIT), 256>>>(p_x2, p_x2, fc2_w, HH, 64, p_x3p);
    // 7) reduce + bias -> out
    k_red<<<256, 256>>>(fc2_b, p_x3p, out_x);
}